// round 5
// baseline (speedup 1.0000x reference)
#include <cuda_runtime.h>
#include <cuda_bf16.h>
#include <math.h>
#include <stdint.h>

#define BATCH 4
#define SEQ   2048
#define DIM   512
#define UDIM  256
#define MROWS (BATCH*SEQ)

// ---------------- scratch (device globals) ---------------------------------
// packed-split bf16: per 32-k chunk 128B = [32 bf16 hi][32 bf16 lo]
__device__ __align__(128) unsigned char g_xps [(size_t)MROWS*DIM*4];
__device__ __align__(128) unsigned char g_wps [(size_t)3*UDIM*DIM*4];
__device__ __align__(128) unsigned char g_qps [(size_t)MROWS*UDIM*4];
__device__ __align__(128) unsigned char g_kps [(size_t)MROWS*UDIM*4];
__device__ __align__(128) float         g_v   [(size_t)MROWS*UDIM];
__device__ __align__(128) unsigned char g_vtps[(size_t)BATCH*UDIM*SEQ*4];
__device__ __align__(128) float         g_s   [(size_t)BATCH*SEQ*SEQ];
__device__ __align__(128) float2        g_part[(size_t)MROWS*16];
__device__ __align__(128) float         g_shift[(size_t)MROWS];

// ---------------- helpers ---------------------------------------------------
__device__ __forceinline__ uint32_t smem_u32(const void* p){
    uint32_t a;
    asm("{ .reg .u64 t; cvta.to.shared.u64 t, %1; cvt.u32.u64 %0, t; }" : "=r"(a) : "l"(p));
    return a;
}
__device__ __forceinline__ uint32_t sw128(uint32_t off){ return off ^ ((off>>3)&0x70); }

__device__ __forceinline__ uint32_t packbf(__nv_bfloat16 a, __nv_bfloat16 b){
    __nv_bfloat162 t; t.x = a; t.y = b;
    return *reinterpret_cast<uint32_t*>(&t);
}
__device__ __forceinline__ void split2(float a, float b, uint32_t& hi, uint32_t& lo){
    __nv_bfloat16 ha = __float2bfloat16(a), hb = __float2bfloat16(b);
    hi = packbf(ha, hb);
    lo = packbf(__float2bfloat16(a - __bfloat162float(ha)),
                __float2bfloat16(b - __bfloat162float(hb)));
}
__device__ __forceinline__ void split4(float4 v, uint2& hi, uint2& lo){
    split2(v.x, v.y, hi.x, lo.x);
    split2(v.z, v.w, hi.y, lo.y);
}

__device__ __forceinline__ void cpa16(uint32_t dst, const void* src){
    asm volatile("cp.async.cg.shared.global [%0], [%1], 16;" :: "r"(dst), "l"(src));
}
__device__ __forceinline__ void cpa_commit(){ asm volatile("cp.async.commit_group;" ::: "memory"); }
template<int N> __device__ __forceinline__ void cpa_wait(){
    asm volatile("cp.async.wait_group %0;" :: "n"(N) : "memory");
}
__device__ __forceinline__ void ldm_x4(uint32_t* r, uint32_t addr){
    asm volatile("ldmatrix.sync.aligned.m8n8.x4.shared.b16 {%0,%1,%2,%3}, [%4];"
                 : "=r"(r[0]), "=r"(r[1]), "=r"(r[2]), "=r"(r[3]) : "r"(addr));
}
#define MMA16816(d, a, b0v, b1v) \
    asm volatile("mma.sync.aligned.m16n8k16.row.col.f32.bf16.bf16.f32 " \
                 "{%0,%1,%2,%3},{%4,%5,%6,%7},{%8,%9},{%0,%1,%2,%3};" \
                 : "+f"((d)[0]), "+f"((d)[1]), "+f"((d)[2]), "+f"((d)[3]) \
                 : "r"((a)[0]), "r"((a)[1]), "r"((a)[2]), "r"((a)[3]), \
                   "r"(b0v), "r"(b1v))

// term-major MMA block: 8 independent MMAs between same-acc reuse
#define MMA_BLOCK(acc, ah, al, bh, bl) \
    { \
        _Pragma("unroll") \
        for (int mt = 0; mt < 2; mt++) { _Pragma("unroll") \
            for (int nt = 0; nt < 4; nt++) { \
                const int np = nt >> 1, ix = (nt & 1) * 2; \
                MMA16816(acc[mt][nt], ah[mt], bh[np][ix], bh[np][ix+1]); } } \
        _Pragma("unroll") \
        for (int mt = 0; mt < 2; mt++) { _Pragma("unroll") \
            for (int nt = 0; nt < 4; nt++) { \
                const int np = nt >> 1, ix = (nt & 1) * 2; \
                MMA16816(acc[mt][nt], ah[mt], bl[np][ix], bl[np][ix+1]); } } \
        _Pragma("unroll") \
        for (int mt = 0; mt < 2; mt++) { _Pragma("unroll") \
            for (int nt = 0; nt < 4; nt++) { \
                const int np = nt >> 1, ix = (nt & 1) * 2; \
                MMA16816(acc[mt][nt], al[mt], bh[np][ix], bh[np][ix+1]); } } \
    }

// ---------------- generic ps GEMM -------------------------------------------
// C[M,N] = A[M,K]*B[N,K]^T on packed-split operands. CTA 128x128, 512 thr,
// warp 32x32, K-chunk 32, 4-stage cp.async.
// MODE 0: fp32 out. MODE 2: fp32 out + per-row (m,l) partial stats.
// MODE 3: QKV router (col<256 -> Cq ps, <512 -> Ck ps, else Cv fp32).
#define STAGES    4
#define STG_BYTES 16384
#define SMEM_GEMM (STAGES*2*STG_BYTES)   // 128 KB

template<int MODE>
__global__ __launch_bounds__(512)
void gemm_ps(const unsigned char* __restrict__ A, const unsigned char* __restrict__ B,
             float* __restrict__ Cf, unsigned char* __restrict__ Cq,
             unsigned char* __restrict__ Ck, float* __restrict__ Cv,
             float2* __restrict__ part,
             int K, int pitchA, int pitchB, int ldC,
             size_t sA, size_t sB, size_t sC)
{
    extern __shared__ char smem[];
    __shared__ float2 stat_sm[4][32][4];
    A += (size_t)blockIdx.z * sA;
    B += (size_t)blockIdx.z * sB;

    const int tid = threadIdx.x;
    const int wid = tid >> 5, lt = tid & 31;
    const int warpM = (wid & 3) * 32, warpN = (wid >> 2) * 32;
    const int rowBase = blockIdx.y * 128, colBase = blockIdx.x * 128;

    const int lr = tid >> 2;
    const int lg = (tid & 3) * 32;
    const uint32_t mask = (uint32_t)(lr & 7) * 16;
    const uint32_t o1 = (uint32_t)lr * 128 + ((uint32_t)lg ^ mask);
    const uint32_t o2 = o1 ^ 16;
    const unsigned char* gA = A + (size_t)(rowBase + lr) * pitchA + lg;
    const unsigned char* gB = B + (size_t)(colBase + lr) * pitchB + lg;

    const uint32_t sb = smem_u32(smem);
    const int nch = K / 32;

    const uint32_t aOff = (uint32_t)((warpM + (lt & 15)) * 128 + ((lt >> 4) & 1) * 16);
    const uint32_t bOff = (uint32_t)((warpN + (lt & 7) + ((lt >> 4) & 1) * 8) * 128
                                     + ((lt >> 3) & 1) * 16);

    float acc[2][4][4];
    #pragma unroll
    for (int i = 0; i < 2; i++)
        #pragma unroll
        for (int j = 0; j < 4; j++)
            #pragma unroll
            for (int e = 0; e < 4; e++) acc[i][j][e] = 0.f;

    #pragma unroll
    for (int st = 0; st < 3; st++) {
        uint32_t base = sb + (uint32_t)st * (2*STG_BYTES);
        const unsigned char* pa = gA + (size_t)st * 128;
        const unsigned char* pb = gB + (size_t)st * 128;
        cpa16(base + o1, pa);                 cpa16(base + o2, pa + 16);
        cpa16(base + STG_BYTES + o1, pb);     cpa16(base + STG_BYTES + o2, pb + 16);
        cpa_commit();
    }

    for (int c = 0; c < nch; c++) {
        cpa_wait<2>();
        __syncthreads();

        if (c + 3 < nch) {
            uint32_t base = sb + (uint32_t)((c + 3) & 3) * (2*STG_BYTES);
            const unsigned char* pa = gA + (size_t)(c + 3) * 128;
            const unsigned char* pb = gB + (size_t)(c + 3) * 128;
            cpa16(base + o1, pa);                 cpa16(base + o2, pa + 16);
            cpa16(base + STG_BYTES + o1, pb);     cpa16(base + STG_BYTES + o2, pb + 16);
        }
        cpa_commit();

        const uint32_t aB = sb + (uint32_t)(c & 3) * (2*STG_BYTES);
        const uint32_t bB = aB + STG_BYTES;

        #pragma unroll
        for (int s = 0; s < 2; s++) {
            uint32_t ah[2][4], al[2][4], bh[2][4], bl[2][4];
            #pragma unroll
            for (int mt = 0; mt < 2; mt++) {
                uint32_t o = aOff + (uint32_t)mt * 2048 + (uint32_t)s * 32;
                ldm_x4(ah[mt], aB + sw128(o));
                ldm_x4(al[mt], aB + sw128(o + 64));
            }
            #pragma unroll
            for (int np = 0; np < 2; np++) {
                uint32_t o = bOff + (uint32_t)np * 2048 + (uint32_t)s * 32;
                ldm_x4(bh[np], bB + sw128(o));
                ldm_x4(bl[np], bB + sw128(o + 64));
            }
            MMA_BLOCK(acc, ah, al, bh, bl);
        }
    }

    // ---- epilogue ----
    if (MODE == 3) {
        // QKV router
        #pragma unroll
        for (int mt = 0; mt < 2; mt++) {
            const int r0 = rowBase + warpM + mt * 16 + (lt >> 2);
            #pragma unroll
            for (int nt = 0; nt < 4; nt++) {
                const int col = colBase + warpN + nt * 8 + (lt & 3) * 2;
                if (col < 512) {
                    unsigned char* base = (col < 256) ? Cq : Ck;
                    const int cc = col & 255;
                    const uint32_t cb = (uint32_t)(cc >> 5) * 128 + (uint32_t)(cc & 31) * 2;
                    uint32_t hi, lo;
                    split2(acc[mt][nt][0], acc[mt][nt][1], hi, lo);
                    unsigned char* p0 = base + (size_t)r0 * (UDIM*4) + cb;
                    *(uint32_t*)p0        = hi;
                    *(uint32_t*)(p0 + 64) = lo;
                    split2(acc[mt][nt][2], acc[mt][nt][3], hi, lo);
                    unsigned char* p1 = base + (size_t)(r0 + 8) * (UDIM*4) + cb;
                    *(uint32_t*)p1        = hi;
                    *(uint32_t*)(p1 + 64) = lo;
                } else {
                    const int cc = col - 512;
                    *(float2*)&Cv[(size_t)r0 * UDIM + cc] =
                        make_float2(acc[mt][nt][0], acc[mt][nt][1]);
                    *(float2*)&Cv[(size_t)(r0 + 8) * UDIM + cc] =
                        make_float2(acc[mt][nt][2], acc[mt][nt][3]);
                }
            }
        }
        return;
    }

    {
        float* C = Cf + (size_t)blockIdx.z * sC;
        #pragma unroll
        for (int mt = 0; mt < 2; mt++) {
            const int r0 = rowBase + warpM + mt * 16 + (lt >> 2);
            #pragma unroll
            for (int nt = 0; nt < 4; nt++) {
                const int cc = colBase + warpN + nt * 8 + (lt & 3) * 2;
                *(float2*)&C[(size_t)r0 * ldC + cc] =
                    make_float2(acc[mt][nt][0], acc[mt][nt][1]);
                *(float2*)&C[(size_t)(r0 + 8) * ldC + cc] =
                    make_float2(acc[mt][nt][2], acc[mt][nt][3]);
            }
        }
    }

    if (MODE == 2) {
        // per-row (max, sum exp) over this CTA's 128 columns
        #pragma unroll
        for (int mt = 0; mt < 2; mt++) {
            #pragma unroll
            for (int half = 0; half < 2; half++) {
                float m = -INFINITY;
                #pragma unroll
                for (int nt = 0; nt < 4; nt++) {
                    m = fmaxf(m, fmaxf(acc[mt][nt][half*2], acc[mt][nt][half*2+1]));
                }
                float l = 0.f;
                #pragma unroll
                for (int nt = 0; nt < 4; nt++) {
                    l += __expf(acc[mt][nt][half*2]   - m);
                    l += __expf(acc[mt][nt][half*2+1] - m);
                }
                #pragma unroll
                for (int off = 1; off <= 2; off <<= 1) {
                    float om = __shfl_xor_sync(0xffffffffu, m, off);
                    float ol = __shfl_xor_sync(0xffffffffu, l, off);
                    float nm = fmaxf(m, om);
                    l = l * __expf(m - nm) + ol * __expf(om - nm);
                    m = nm;
                }
                if ((lt & 3) == 0) {
                    const int rloc = mt * 16 + half * 8 + (lt >> 2);
                    stat_sm[wid & 3][rloc][wid >> 2] = make_float2(m, l);
                }
            }
        }
        __syncthreads();
        if (tid < 128) {
            const int mw = tid >> 5, r = tid & 31;
            float2 a = stat_sm[mw][r][0];
            float m = a.x, l = a.y;
            #pragma unroll
            for (int j = 1; j < 4; j++) {
                float2 b = stat_sm[mw][r][j];
                float nm = fmaxf(m, b.x);
                l = l * __expf(m - nm) + b.y * __expf(b.x - nm);
                m = nm;
            }
            const size_t grow = (size_t)blockIdx.z * SEQ + rowBase + mw * 32 + r;
            part[grow * 16 + blockIdx.x] = make_float2(m, l);
        }
    }
}

// ---------------- combine per-row partials -> shift = m + log(l) -----------
__global__ __launch_bounds__(256)
void rowstat_combine(const float2* __restrict__ part, float* __restrict__ shift)
{
    const int r = blockIdx.x * 256 + threadIdx.x;
    const float2* p = part + (size_t)r * 16;
    float m = -INFINITY;
    #pragma unroll
    for (int j = 0; j < 16; j++) m = fmaxf(m, p[j].x);
    float l = 0.f;
    #pragma unroll
    for (int j = 0; j < 16; j++) l += p[j].y * __expf(p[j].x - m);
    shift[r] = m + logf(l);
}

// ---------------- PV GEMM: A = exp(S - shift) computed on the fly ----------
// C[M,N] = P[M,K]*B[N,K]^T, P derived from fp32 S. A register-staged,
// B 4-stage cp.async. smem: A ps 2x16KB + B 4x16KB = 96KB.
#define SMEM_PV (2*STG_BYTES + 4*STG_BYTES)

__global__ __launch_bounds__(512)
void gemm_pv(const float* __restrict__ S, const float* __restrict__ shift,
             const unsigned char* __restrict__ B, float* __restrict__ C,
             int K, int pitchB,
             size_t sS, size_t sB, size_t sC)
{
    extern __shared__ char smem[];
    S += (size_t)blockIdx.z * sS;
    B += (size_t)blockIdx.z * sB;
    C += (size_t)blockIdx.z * sC;

    const int tid = threadIdx.x;
    const int wid = tid >> 5, lt = tid & 31;
    const int warpM = (wid & 3) * 32, warpN = (wid >> 2) * 32;
    const int rowBase = blockIdx.y * 128, colBase = blockIdx.x * 128;

    // A staging: thread -> row lr (0..127), 8 cols starting at k0
    const int lr = tid >> 2;
    const int k0 = (tid & 3) * 8;
    const float* gA = S + (size_t)(rowBase + lr) * SEQ + k0;
    const float shv = shift[(size_t)blockIdx.z * SEQ + rowBase + lr];
    const uint32_t aStHi = sw128((uint32_t)lr * 128 + (uint32_t)k0 * 2);
    const uint32_t aStLo = sw128((uint32_t)lr * 128 + (uint32_t)k0 * 2 + 64);

    // B cp.async mapping (same as gemm_ps)
    const int blr = tid >> 2;
    const int blg = (tid & 3) * 32;
    const uint32_t bmask = (uint32_t)(blr & 7) * 16;
    const uint32_t bo1 = (uint32_t)blr * 128 + ((uint32_t)blg ^ bmask);
    const uint32_t bo2 = bo1 ^ 16;
    const unsigned char* gB = B + (size_t)(colBase + blr) * pitchB + blg;

    const uint32_t sb = smem_u32(smem);
    const uint32_t aBufs = sb;                 // 2 x 16KB
    const uint32_t bBufs = sb + 2*STG_BYTES;   // 4 x 16KB

    const int nch = K / 32;

    const uint32_t aOff = (uint32_t)((warpM + (lt & 15)) * 128 + ((lt >> 4) & 1) * 16);
    const uint32_t bOff = (uint32_t)((warpN + (lt & 7) + ((lt >> 4) & 1) * 8) * 128
                                     + ((lt >> 3) & 1) * 16);

    float acc[2][4][4];
    #pragma unroll
    for (int i = 0; i < 2; i++)
        #pragma unroll
        for (int j = 0; j < 4; j++)
            #pragma unroll
            for (int e = 0; e < 4; e++) acc[i][j][e] = 0.f;

    // ---- prologue ----
    float4 fa0, fa1;
    {   // chunk 0 -> A buf 0
        fa0 = *(const float4*)(gA);
        fa1 = *(const float4*)(gA + 4);
        float4 p0 = make_float4(__expf(fa0.x - shv), __expf(fa0.y - shv),
                                __expf(fa0.z - shv), __expf(fa0.w - shv));
        float4 p1 = make_float4(__expf(fa1.x - shv), __expf(fa1.y - shv),
                                __expf(fa1.z - shv), __expf(fa1.w - shv));
        uint2 h0, l0, h1, l1;
        split4(p0, h0, l0); split4(p1, h1, l1);
        *(uint4*)(smem + aStHi) = make_uint4(h0.x, h0.y, h1.x, h1.y);
        *(uint4*)(smem + aStLo) = make_uint4(l0.x, l0.y, l1.x, l1.y);
    }
    // chunk 1 -> regs
    fa0 = *(const float4*)(gA + 32);
    fa1 = *(const float4*)(gA + 36);
    // B stages 0..2
    #pragma unroll
    for (int st = 0; st < 3; st++) {
        uint32_t base = bBufs + (uint32_t)st * STG_BYTES;
        const unsigned char* pb = gB + (size_t)st * 128;
        cpa16(base + bo1, pb);  cpa16(base + bo2, pb + 16);
        cpa_commit();
    }

    for (int c = 0; c < nch; c++) {
        cpa_wait<2>();
        __syncthreads();

        // issue B_{c+3}
        if (c + 3 < nch) {
            uint32_t base = bBufs + (uint32_t)((c + 3) & 3) * STG_BYTES;
            const unsigned char* pb = gB + (size_t)(c + 3) * 128;
            cpa16(base + bo1, pb);  cpa16(base + bo2, pb + 16);
        }
        cpa_commit();

        const uint32_t aB = aBufs + (uint32_t)(c & 1) * STG_BYTES;
        const uint32_t bB = bBufs + (uint32_t)(c & 3) * STG_BYTES;

        #pragma unroll
        for (int s = 0; s < 2; s++) {
            uint32_t ah[2][4], al[2][4], bh[2][4], bl[2][4];
            #pragma unroll
            for (int mt = 0; mt < 2; mt++) {
                uint32_t o = aOff + (uint32_t)mt * 2048 + (uint32_t)s * 32;
                ldm_x4(ah[mt], aB + sw128(o));
                ldm_x4(al[mt], aB + sw128(o + 64));
            }
            #pragma unroll
            for (int np = 0; np < 2; np++) {
                uint32_t o = bOff + (uint32_t)np * 2048 + (uint32_t)s * 32;
                ldm_x4(bh[np], bB + sw128(o));
                ldm_x4(bl[np], bB + sw128(o + 64));
            }
            MMA_BLOCK(acc, ah, al, bh, bl);
        }

        // split staged chunk c+1, prefetch chunk c+2
        if (c + 1 < nch) {
            char* dA = smem + (uint32_t)((c + 1) & 1) * STG_BYTES;
            float4 p0 = make_float4(__expf(fa0.x - shv), __expf(fa0.y - shv),
                                    __expf(fa0.z - shv), __expf(fa0.w - shv));
            float4 p1 = make_float4(__expf(fa1.x - shv), __expf(fa1.y - shv),
                                    __expf(fa1.z - shv), __expf(fa1.w - shv));
            uint2 h0, l0, h1, l1;
            split4(p0, h0, l0); split4(p1, h1, l1);
            *(uint4*)(dA + aStHi) = make_uint4(h0.x, h0.y, h1.x, h1.y);
            *(uint4*)(dA + aStLo) = make_uint4(l0.x, l0.y, l1.x, l1.y);
            if (c + 2 < nch) {
                fa0 = *(const float4*)(gA + (size_t)(c + 2) * 32);
                fa1 = *(const float4*)(gA + (size_t)(c + 2) * 32 + 4);
            }
        }
    }

    #pragma unroll
    for (int mt = 0; mt < 2; mt++) {
        const int r0 = rowBase + warpM + mt * 16 + (lt >> 2);
        #pragma unroll
        for (int nt = 0; nt < 4; nt++) {
            const int cc = colBase + warpN + nt * 8 + (lt & 3) * 2;
            *(float2*)&C[(size_t)r0 * UDIM + cc] =
                make_float2(acc[mt][nt][0], acc[mt][nt][1]);
            *(float2*)&C[(size_t)(r0 + 8) * UDIM + cc] =
                make_float2(acc[mt][nt][2], acc[mt][nt][3]);
        }
    }
}

// ---------------- split fp32 -> packed-split --------------------------------
__global__ __launch_bounds__(256)
void split_pack(const float* __restrict__ in, unsigned char* __restrict__ out, int Kelems)
{
    const size_t idx = ((size_t)blockIdx.x * 256 + threadIdx.x) * 8;
    const size_t row = idx / Kelems;
    const int k0 = (int)(idx % Kelems);
    float4 f0 = *(const float4*)(in + idx);
    float4 f1 = *(const float4*)(in + idx + 4);
    uint2 h0, l0, h1, l1;
    split4(f0, h0, l0);
    split4(f1, h1, l1);
    unsigned char* p = out + row * ((size_t)Kelems * 4) + (k0 >> 5) * 128 + (k0 & 31) * 2;
    *(uint4*)p        = make_uint4(h0.x, h0.y, h1.x, h1.y);
    *(uint4*)(p + 64) = make_uint4(l0.x, l0.y, l1.x, l1.y);
}

// ---------------- transpose [R,C] fp32 -> packed-split [C rows, R k] --------
__global__ __launch_bounds__(256)
void transpose_split(const float* __restrict__ in, unsigned char* __restrict__ out,
                     int R, int C, size_t sIn, size_t sOut)
{
    __shared__ float t[32][33];
    in  += (size_t)blockIdx.z * sIn;
    out += (size_t)blockIdx.z * sOut;
    const int tid = threadIdx.x;
    const int tx = tid & 31, ty = tid >> 5;
    int x = blockIdx.x * 32 + tx;
    int y = blockIdx.y * 32 + ty;
    #pragma unroll
    for (int j = 0; j < 32; j += 8)
        t[ty + j][tx] = in[(size_t)(y + j) * C + x];
    __syncthreads();

    const int wr = tid >> 3;
    const int wg = tid & 7;
    float f0 = t[wg*4 + 0][wr];
    float f1 = t[wg*4 + 1][wr];
    float f2 = t[wg*4 + 2][wr];
    float f3 = t[wg*4 + 3][wr];
    uint32_t h0, l0, h1, l1;
    split2(f0, f1, h0, l0);
    split2(f2, f3, h1, l1);
    const size_t pitch = (size_t)R * 4;
    unsigned char* p = out + (size_t)(blockIdx.x * 32 + wr) * pitch
                           + (size_t)blockIdx.y * 128 + wg * 8;
    *(uint2*)p        = make_uint2(h0, h1);
    *(uint2*)(p + 64) = make_uint2(l0, l1);
}

// ---------------- launch ----------------------------------------------------
extern "C" void kernel_launch(void* const* d_in, const int* in_sizes, int n_in,
                              void* d_out, int out_size)
{
    const float* x  = (const float*)d_in[0];
    const float* Wq = (const float*)d_in[1];
    const float* Wk = (const float*)d_in[2];
    const float* Wv = (const float*)d_in[3];
    float* out = (float*)d_out;

    unsigned char *xps, *wps, *qps, *kps, *vtps;
    float *v, *s, *shift;
    float2 *part;
    cudaGetSymbolAddress((void**)&xps,  g_xps);
    cudaGetSymbolAddress((void**)&wps,  g_wps);
    cudaGetSymbolAddress((void**)&qps,  g_qps);
    cudaGetSymbolAddress((void**)&kps,  g_kps);
    cudaGetSymbolAddress((void**)&v,    g_v);
    cudaGetSymbolAddress((void**)&vtps, g_vtps);
    cudaGetSymbolAddress((void**)&s,    g_s);
    cudaGetSymbolAddress((void**)&part, g_part);
    cudaGetSymbolAddress((void**)&shift, g_shift);

    cudaFuncSetAttribute(gemm_ps<0>, cudaFuncAttributeMaxDynamicSharedMemorySize, SMEM_GEMM);
    cudaFuncSetAttribute(gemm_ps<2>, cudaFuncAttributeMaxDynamicSharedMemorySize, SMEM_GEMM);
    cudaFuncSetAttribute(gemm_ps<3>, cudaFuncAttributeMaxDynamicSharedMemorySize, SMEM_GEMM);
    cudaFuncSetAttribute(gemm_pv,    cudaFuncAttributeMaxDynamicSharedMemorySize, SMEM_PV);

    const size_t WPS = (size_t)UDIM * DIM * 4;

    // 1) split x; transpose+split weights (concatenated [Wq;Wk;Wv] -> 768 rows)
    split_pack<<<(MROWS*DIM)/(256*8), 256>>>(x, xps, DIM);
    transpose_split<<<dim3(UDIM/32, DIM/32, 1), 256>>>(Wq, wps + 0*WPS, DIM, UDIM, 0, 0);
    transpose_split<<<dim3(UDIM/32, DIM/32, 1), 256>>>(Wk, wps + 1*WPS, DIM, UDIM, 0, 0);
    transpose_split<<<dim3(UDIM/32, DIM/32, 1), 256>>>(Wv, wps + 2*WPS, DIM, UDIM, 0, 0);

    // 2) fused QKV: [8192,512] x [768,512]^T, router epilogue
    {
        dim3 g(768/128, MROWS/128, 1);
        gemm_ps<3><<<g, 512, SMEM_GEMM>>>(xps, wps, nullptr, qps, kps, v, nullptr,
                                          DIM, DIM*4, DIM*4, 0, 0, 0, 0);
    }

    // 3) v -> vt packed-split per batch
    transpose_split<<<dim3(UDIM/32, SEQ/32, BATCH), 256>>>(v, vtps, SEQ, UDIM,
        (size_t)SEQ*UDIM, (size_t)UDIM*SEQ*4);

    // 4) scores = Q K^T with fused row stats
    {
        dim3 g(SEQ/128, SEQ/128, BATCH);
        gemm_ps<2><<<g, 512, SMEM_GEMM>>>(qps, kps, s, nullptr, nullptr, nullptr, part,
                                          UDIM, UDIM*4, UDIM*4, SEQ,
                                          (size_t)SEQ*UDIM*4, (size_t)SEQ*UDIM*4,
                                          (size_t)SEQ*SEQ);
    }

    // 5) combine stats -> shift
    rowstat_combine<<<MROWS/256, 256>>>(part, shift);

    // 6) out = softmax(S) V with exp fused into the A path
    {
        dim3 g(UDIM/128, SEQ/128, BATCH);
        gemm_pv<<<g, 512, SMEM_PV>>>(s, shift, vtps, out,
                                     SEQ, SEQ*4,
                                     (size_t)SEQ*SEQ, (size_t)UDIM*SEQ*4,
                                     (size_t)SEQ*UDIM);
    }
}

// round 6
// speedup vs baseline: 1.0341x; 1.0341x over previous
#include <cuda_runtime.h>
#include <cuda_bf16.h>
#include <cuda_fp16.h>
#include <math.h>
#include <stdint.h>

#define BATCH 4
#define SEQ   2048
#define DIM   512
#define UDIM  256
#define MROWS (BATCH*SEQ)

// ---------------- scratch (device globals) ---------------------------------
// packed-split: per 32-k chunk 128B = [32 hi][32 lo] (bf16 or fp16 content)
__device__ __align__(128) unsigned char g_xps [(size_t)MROWS*DIM*4];
__device__ __align__(128) unsigned char g_wps [(size_t)3*UDIM*DIM*4];
__device__ __align__(128) unsigned char g_qps [(size_t)MROWS*UDIM*4];
__device__ __align__(128) unsigned char g_kps [(size_t)MROWS*UDIM*4];
__device__ __align__(128) float         g_v   [(size_t)MROWS*UDIM];
__device__ __align__(128) unsigned char g_vtps[(size_t)BATCH*UDIM*SEQ*4];
__device__ __align__(128) float         g_s   [(size_t)BATCH*SEQ*SEQ];
__device__ __align__(128) float2        g_part[(size_t)MROWS*16];
__device__ __align__(128) float         g_shift[(size_t)MROWS];

// ---------------- helpers ---------------------------------------------------
__device__ __forceinline__ uint32_t smem_u32(const void* p){
    uint32_t a;
    asm("{ .reg .u64 t; cvta.to.shared.u64 t, %1; cvt.u32.u64 %0, t; }" : "=r"(a) : "l"(p));
    return a;
}
__device__ __forceinline__ uint32_t sw128(uint32_t off){ return off ^ ((off>>3)&0x70); }

__device__ __forceinline__ uint32_t packbf(__nv_bfloat16 a, __nv_bfloat16 b){
    __nv_bfloat162 t; t.x = a; t.y = b;
    return *reinterpret_cast<uint32_t*>(&t);
}
__device__ __forceinline__ void split2(float a, float b, uint32_t& hi, uint32_t& lo){
    __nv_bfloat16 ha = __float2bfloat16(a), hb = __float2bfloat16(b);
    hi = packbf(ha, hb);
    lo = packbf(__float2bfloat16(a - __bfloat162float(ha)),
                __float2bfloat16(b - __bfloat162float(hb)));
}
__device__ __forceinline__ void split4(float4 v, uint2& hi, uint2& lo){
    split2(v.x, v.y, hi.x, lo.x);
    split2(v.z, v.w, hi.y, lo.y);
}
__device__ __forceinline__ uint32_t packh(float a, float b){
    __half2 h = __floats2half2_rn(a, b);
    return *reinterpret_cast<uint32_t*>(&h);
}
__device__ __forceinline__ void split2h(float a, float b, uint32_t& hi, uint32_t& lo){
    __half ha = __float2half_rn(a), hb = __float2half_rn(b);
    hi = packh(__half2float(ha), __half2float(hb));
    lo = packh(a - __half2float(ha), b - __half2float(hb));
}

// fast exp for x <= 0, ~1e-7 rel err, FMA/ALU pipes only (no MUFU)
__device__ __forceinline__ float fexp(float x){
    float t = x * 1.44269504088896f;
    t = fmaxf(t, -120.f);
    float rn = t + 12582912.f;                       // 1.5*2^23 round-to-int
    int   ki = (__float_as_int(rn) & 0x7FFFFF) - 0x400000;
    float f  = t - (rn - 12582912.f);                // f in [-0.5, 0.5]
    float p = fmaf(f, 0.00961812910762848f, 0.0555041086648216f);
    p = fmaf(f, p, 0.240226506959101f);
    p = fmaf(f, p, 0.693147180559945f);
    p = fmaf(f, p, 1.0f);
    return __int_as_float(__float_as_int(p) + (ki << 23));
}

__device__ __forceinline__ void cpa16(uint32_t dst, const void* src){
    asm volatile("cp.async.cg.shared.global [%0], [%1], 16;" :: "r"(dst), "l"(src));
}
__device__ __forceinline__ void cpa_commit(){ asm volatile("cp.async.commit_group;" ::: "memory"); }
template<int N> __device__ __forceinline__ void cpa_wait(){
    asm volatile("cp.async.wait_group %0;" :: "n"(N) : "memory");
}
__device__ __forceinline__ void ldm_x4(uint32_t* r, uint32_t addr){
    asm volatile("ldmatrix.sync.aligned.m8n8.x4.shared.b16 {%0,%1,%2,%3}, [%4];"
                 : "=r"(r[0]), "=r"(r[1]), "=r"(r[2]), "=r"(r[3]) : "r"(addr));
}
#define MMA16816(d, a, b0v, b1v) \
    asm volatile("mma.sync.aligned.m16n8k16.row.col.f32.bf16.bf16.f32 " \
                 "{%0,%1,%2,%3},{%4,%5,%6,%7},{%8,%9},{%0,%1,%2,%3};" \
                 : "+f"((d)[0]), "+f"((d)[1]), "+f"((d)[2]), "+f"((d)[3]) \
                 : "r"((a)[0]), "r"((a)[1]), "r"((a)[2]), "r"((a)[3]), \
                   "r"(b0v), "r"(b1v))
#define MMA16816H(d, a, b0v, b1v) \
    asm volatile("mma.sync.aligned.m16n8k16.row.col.f32.f16.f16.f32 " \
                 "{%0,%1,%2,%3},{%4,%5,%6,%7},{%8,%9},{%0,%1,%2,%3};" \
                 : "+f"((d)[0]), "+f"((d)[1]), "+f"((d)[2]), "+f"((d)[3]) \
                 : "r"((a)[0]), "r"((a)[1]), "r"((a)[2]), "r"((a)[3]), \
                   "r"(b0v), "r"(b1v))

#define MMA_BLOCK(acc, ah, al, bh, bl) \
    { \
        _Pragma("unroll") \
        for (int mt = 0; mt < 2; mt++) { _Pragma("unroll") \
            for (int nt = 0; nt < 4; nt++) { \
                const int np = nt >> 1, ix = (nt & 1) * 2; \
                MMA16816(acc[mt][nt], ah[mt], bh[np][ix], bh[np][ix+1]); } } \
        _Pragma("unroll") \
        for (int mt = 0; mt < 2; mt++) { _Pragma("unroll") \
            for (int nt = 0; nt < 4; nt++) { \
                const int np = nt >> 1, ix = (nt & 1) * 2; \
                MMA16816(acc[mt][nt], ah[mt], bl[np][ix], bl[np][ix+1]); } } \
        _Pragma("unroll") \
        for (int mt = 0; mt < 2; mt++) { _Pragma("unroll") \
            for (int nt = 0; nt < 4; nt++) { \
                const int np = nt >> 1, ix = (nt & 1) * 2; \
                MMA16816(acc[mt][nt], al[mt], bh[np][ix], bh[np][ix+1]); } } \
    }

// ---------------- generic bf16x3 ps GEMM ------------------------------------
#define STAGES    4
#define STG_BYTES 16384
#define SMEM_GEMM (STAGES*2*STG_BYTES)   // 128 KB

template<int MODE>
__global__ __launch_bounds__(512)
void gemm_ps(const unsigned char* __restrict__ A, const unsigned char* __restrict__ B,
             float* __restrict__ Cf, unsigned char* __restrict__ Cq,
             unsigned char* __restrict__ Ck, float* __restrict__ Cv,
             float2* __restrict__ part,
             int K, int pitchA, int pitchB, int ldC,
             size_t sA, size_t sB, size_t sC)
{
    extern __shared__ char smem[];
    __shared__ float2 stat_sm[4][32][4];
    A += (size_t)blockIdx.z * sA;
    B += (size_t)blockIdx.z * sB;

    const int tid = threadIdx.x;
    const int wid = tid >> 5, lt = tid & 31;
    const int warpM = (wid & 3) * 32, warpN = (wid >> 2) * 32;
    const int rowBase = blockIdx.y * 128, colBase = blockIdx.x * 128;

    const int lr = tid >> 2;
    const int lg = (tid & 3) * 32;
    const uint32_t mask = (uint32_t)(lr & 7) * 16;
    const uint32_t o1 = (uint32_t)lr * 128 + ((uint32_t)lg ^ mask);
    const uint32_t o2 = o1 ^ 16;
    const unsigned char* gA = A + (size_t)(rowBase + lr) * pitchA + lg;
    const unsigned char* gB = B + (size_t)(colBase + lr) * pitchB + lg;

    const uint32_t sb = smem_u32(smem);
    const int nch = K / 32;

    const uint32_t aOff = (uint32_t)((warpM + (lt & 15)) * 128 + ((lt >> 4) & 1) * 16);
    const uint32_t bOff = (uint32_t)((warpN + (lt & 7) + ((lt >> 4) & 1) * 8) * 128
                                     + ((lt >> 3) & 1) * 16);

    float acc[2][4][4];
    #pragma unroll
    for (int i = 0; i < 2; i++)
        #pragma unroll
        for (int j = 0; j < 4; j++)
            #pragma unroll
            for (int e = 0; e < 4; e++) acc[i][j][e] = 0.f;

    #pragma unroll
    for (int st = 0; st < 3; st++) {
        uint32_t base = sb + (uint32_t)st * (2*STG_BYTES);
        const unsigned char* pa = gA + (size_t)st * 128;
        const unsigned char* pb = gB + (size_t)st * 128;
        cpa16(base + o1, pa);                 cpa16(base + o2, pa + 16);
        cpa16(base + STG_BYTES + o1, pb);     cpa16(base + STG_BYTES + o2, pb + 16);
        cpa_commit();
    }

    for (int c = 0; c < nch; c++) {
        cpa_wait<2>();
        __syncthreads();

        if (c + 3 < nch) {
            uint32_t base = sb + (uint32_t)((c + 3) & 3) * (2*STG_BYTES);
            const unsigned char* pa = gA + (size_t)(c + 3) * 128;
            const unsigned char* pb = gB + (size_t)(c + 3) * 128;
            cpa16(base + o1, pa);                 cpa16(base + o2, pa + 16);
            cpa16(base + STG_BYTES + o1, pb);     cpa16(base + STG_BYTES + o2, pb + 16);
        }
        cpa_commit();

        const uint32_t aB = sb + (uint32_t)(c & 3) * (2*STG_BYTES);
        const uint32_t bB = aB + STG_BYTES;

        #pragma unroll
        for (int s = 0; s < 2; s++) {
            uint32_t ah[2][4], al[2][4], bh[2][4], bl[2][4];
            #pragma unroll
            for (int mt = 0; mt < 2; mt++) {
                uint32_t o = aOff + (uint32_t)mt * 2048 + (uint32_t)s * 32;
                ldm_x4(ah[mt], aB + sw128(o));
                ldm_x4(al[mt], aB + sw128(o + 64));
            }
            #pragma unroll
            for (int np = 0; np < 2; np++) {
                uint32_t o = bOff + (uint32_t)np * 2048 + (uint32_t)s * 32;
                ldm_x4(bh[np], bB + sw128(o));
                ldm_x4(bl[np], bB + sw128(o + 64));
            }
            MMA_BLOCK(acc, ah, al, bh, bl);
        }
    }

    if (MODE == 3) {
        #pragma unroll
        for (int mt = 0; mt < 2; mt++) {
            const int r0 = rowBase + warpM + mt * 16 + (lt >> 2);
            #pragma unroll
            for (int nt = 0; nt < 4; nt++) {
                const int col = colBase + warpN + nt * 8 + (lt & 3) * 2;
                if (col < 512) {
                    unsigned char* base = (col < 256) ? Cq : Ck;
                    const int cc = col & 255;
                    const uint32_t cb = (uint32_t)(cc >> 5) * 128 + (uint32_t)(cc & 31) * 2;
                    uint32_t hi, lo;
                    split2(acc[mt][nt][0], acc[mt][nt][1], hi, lo);
                    unsigned char* p0 = base + (size_t)r0 * (UDIM*4) + cb;
                    *(uint32_t*)p0        = hi;
                    *(uint32_t*)(p0 + 64) = lo;
                    split2(acc[mt][nt][2], acc[mt][nt][3], hi, lo);
                    unsigned char* p1 = base + (size_t)(r0 + 8) * (UDIM*4) + cb;
                    *(uint32_t*)p1        = hi;
                    *(uint32_t*)(p1 + 64) = lo;
                } else {
                    const int cc = col - 512;
                    *(float2*)&Cv[(size_t)r0 * UDIM + cc] =
                        make_float2(acc[mt][nt][0], acc[mt][nt][1]);
                    *(float2*)&Cv[(size_t)(r0 + 8) * UDIM + cc] =
                        make_float2(acc[mt][nt][2], acc[mt][nt][3]);
                }
            }
        }
        return;
    }

    {
        float* C = Cf + (size_t)blockIdx.z * sC;
        #pragma unroll
        for (int mt = 0; mt < 2; mt++) {
            const int r0 = rowBase + warpM + mt * 16 + (lt >> 2);
            #pragma unroll
            for (int nt = 0; nt < 4; nt++) {
                const int cc = colBase + warpN + nt * 8 + (lt & 3) * 2;
                *(float2*)&C[(size_t)r0 * ldC + cc] =
                    make_float2(acc[mt][nt][0], acc[mt][nt][1]);
                *(float2*)&C[(size_t)(r0 + 8) * ldC + cc] =
                    make_float2(acc[mt][nt][2], acc[mt][nt][3]);
            }
        }
    }

    if (MODE == 2) {
        #pragma unroll
        for (int mt = 0; mt < 2; mt++) {
            #pragma unroll
            for (int half = 0; half < 2; half++) {
                float m = -INFINITY;
                #pragma unroll
                for (int nt = 0; nt < 4; nt++)
                    m = fmaxf(m, fmaxf(acc[mt][nt][half*2], acc[mt][nt][half*2+1]));
                float l = 0.f;
                #pragma unroll
                for (int nt = 0; nt < 4; nt++) {
                    l += __expf(acc[mt][nt][half*2]   - m);
                    l += __expf(acc[mt][nt][half*2+1] - m);
                }
                #pragma unroll
                for (int off = 1; off <= 2; off <<= 1) {
                    float om = __shfl_xor_sync(0xffffffffu, m, off);
                    float ol = __shfl_xor_sync(0xffffffffu, l, off);
                    float nm = fmaxf(m, om);
                    l = l * __expf(m - nm) + ol * __expf(om - nm);
                    m = nm;
                }
                if ((lt & 3) == 0) {
                    const int rloc = mt * 16 + half * 8 + (lt >> 2);
                    stat_sm[wid & 3][rloc][wid >> 2] = make_float2(m, l);
                }
            }
        }
        __syncthreads();
        if (tid < 128) {
            const int mw = tid >> 5, r = tid & 31;
            float2 a = stat_sm[mw][r][0];
            float m = a.x, l = a.y;
            #pragma unroll
            for (int j = 1; j < 4; j++) {
                float2 b = stat_sm[mw][r][j];
                float nm = fmaxf(m, b.x);
                l = l * __expf(m - nm) + b.y * __expf(b.x - nm);
                m = nm;
            }
            const size_t grow = (size_t)blockIdx.z * SEQ + rowBase + mw * 32 + r;
            part[grow * 16 + blockIdx.x] = make_float2(m, l);
        }
    }
}

// ---------------- combine -> shift = m + log(l) ------------------------------
__global__ __launch_bounds__(256)
void rowstat_combine(const float2* __restrict__ part, float* __restrict__ shift)
{
    const int r = blockIdx.x * 256 + threadIdx.x;
    const float2* p = part + (size_t)r * 16;
    float m = -INFINITY;
    #pragma unroll
    for (int j = 0; j < 16; j++) m = fmaxf(m, p[j].x);
    float l = 0.f;
    #pragma unroll
    for (int j = 0; j < 16; j++) l += p[j].y * __expf(p[j].x - m);
    shift[r] = m + logf(l);
}

// ---------------- PV GEMM: fp16 2-term, cp.async-staged S + poly exp --------
#define PV_SST  16384
#define PV_SSS  (2*PV_SST)            // 32KB per 64-k superstage of fp32 S
#define PV_AST  16384                 // fp16 A tile (128 rows x 64 k)
#define PV_BSS  (2*16384)             // 32KB per 64-k superstage of Vt limbs
#define SMEM_PV2 (3*PV_SSS + PV_AST + 3*PV_BSS)   // 208 KB

__global__ __launch_bounds__(512)
void gemm_pv2(const float* __restrict__ S, const float* __restrict__ shift,
              const unsigned char* __restrict__ Vt, float* __restrict__ C,
              size_t sS, size_t sV, size_t sC)
{
    extern __shared__ char smem[];
    S  += (size_t)blockIdx.z * sS;
    Vt += (size_t)blockIdx.z * sV;
    C  += (size_t)blockIdx.z * sC;

    const int tid = threadIdx.x;
    const int wid = tid >> 5, lt = tid & 31;
    const int warpM = (wid & 3) * 32, warpN = (wid >> 2) * 32;
    const int rowBase = blockIdx.y * 128, colBase = blockIdx.x * 128;

    const uint32_t sb    = smem_u32(smem);
    const uint32_t Sbase = sb;
    const uint32_t Abase = sb + 3*PV_SSS;
    const uint32_t Bbase = Abase + PV_AST;

    // S staging / conversion mapping: thread -> row sr, 16 floats
    const int sr    = tid >> 2;
    const int q     = tid & 3;
    const int chunk = q >> 1, halfk = q & 1;
    const float* gS = S + (size_t)(rowBase + sr) * SEQ + chunk*32 + halfk*16;
    const float shv = shift[(size_t)blockIdx.z * SEQ + rowBase + sr];
    uint32_t sgOff[4];
    #pragma unroll
    for (int j = 0; j < 4; j++)
        sgOff[j] = (uint32_t)chunk*PV_SST + (uint32_t)sr*128
                 + (uint32_t)(((halfk*4 + j) ^ (sr & 7)) * 16);
    const uint32_t ga   = (uint32_t)(chunk*4 + halfk*2);
    const uint32_t aSt0 = (uint32_t)sr*128 + ((ga ^ (uint32_t)(sr & 7)) * 16);
    const uint32_t aSt1 = aSt0 ^ 16;

    // B staging mapping
    const int blr = tid >> 2;
    const uint32_t blg = (uint32_t)(tid & 3) * 32;
    const uint32_t bo1 = (uint32_t)blr*128 + (blg ^ ((uint32_t)(blr & 7) * 16));
    const uint32_t bo2 = bo1 ^ 16;
    const unsigned char* gB = Vt + (size_t)(colBase + blr) * (SEQ*4) + blg;

    const uint32_t aOff = (uint32_t)((warpM + (lt & 15)) * 128 + ((lt >> 4) & 1) * 16);
    const uint32_t bOff = (uint32_t)((warpN + (lt & 7) + ((lt >> 4) & 1) * 8) * 128
                                     + ((lt >> 3) & 1) * 16);

    float acc[2][4][4];
    #pragma unroll
    for (int i = 0; i < 2; i++)
        #pragma unroll
        for (int j = 0; j < 4; j++)
            #pragma unroll
            for (int e = 0; e < 4; e++) acc[i][j][e] = 0.f;

    const int nsc = SEQ / 64;   // 32

    // prologue: superchunks 0,1
    #pragma unroll
    for (int u = 0; u < 2; u++) {
        uint32_t Sst = Sbase + (uint32_t)(u % 3) * PV_SSS;
        const float* ps = gS + (size_t)u * 64;
        #pragma unroll
        for (int j = 0; j < 4; j++) cpa16(Sst + sgOff[j], ps + j*4);
        uint32_t Bst = Bbase + (uint32_t)(u % 3) * PV_BSS;
        #pragma unroll
        for (int c = 0; c < 2; c++) {
            const unsigned char* pb = gB + (size_t)u * 256 + c * 128;
            cpa16(Bst + (uint32_t)c*16384 + bo1, pb);
            cpa16(Bst + (uint32_t)c*16384 + bo2, pb + 16);
        }
        cpa_commit();
    }

    for (int u = 0; u < nsc; u++) {
        cpa_wait<1>();
        __syncthreads();

        // issue u+2
        if (u + 2 < nsc) {
            const int w = u + 2;
            uint32_t Sst = Sbase + (uint32_t)(w % 3) * PV_SSS;
            const float* ps = gS + (size_t)w * 64;
            #pragma unroll
            for (int j = 0; j < 4; j++) cpa16(Sst + sgOff[j], ps + j*4);
            uint32_t Bst = Bbase + (uint32_t)(w % 3) * PV_BSS;
            #pragma unroll
            for (int c = 0; c < 2; c++) {
                const unsigned char* pb = gB + (size_t)w * 256 + c * 128;
                cpa16(Bst + (uint32_t)c*16384 + bo1, pb);
                cpa16(Bst + (uint32_t)c*16384 + bo2, pb + 16);
            }
        }
        cpa_commit();

        // convert S(u) -> A (fp16, p = exp(s - shift))
        {
            const uint32_t sByte = (uint32_t)(u % 3) * PV_SSS;
            float4 f0 = *(const float4*)(smem + sByte + sgOff[0]);
            float4 f1 = *(const float4*)(smem + sByte + sgOff[1]);
            float4 f2 = *(const float4*)(smem + sByte + sgOff[2]);
            float4 f3 = *(const float4*)(smem + sByte + sgOff[3]);
            uint4 hA, hB;
            hA.x = packh(fexp(f0.x - shv), fexp(f0.y - shv));
            hA.y = packh(fexp(f0.z - shv), fexp(f0.w - shv));
            hA.z = packh(fexp(f1.x - shv), fexp(f1.y - shv));
            hA.w = packh(fexp(f1.z - shv), fexp(f1.w - shv));
            hB.x = packh(fexp(f2.x - shv), fexp(f2.y - shv));
            hB.y = packh(fexp(f2.z - shv), fexp(f2.w - shv));
            hB.z = packh(fexp(f3.x - shv), fexp(f3.y - shv));
            hB.w = packh(fexp(f3.z - shv), fexp(f3.w - shv));
            *(uint4*)(smem + 3*PV_SSS + aSt0) = hA;
            *(uint4*)(smem + 3*PV_SSS + aSt1) = hB;
        }
        __syncthreads();

        // MMA phase: 4 k16 steps, 2 terms each
        const uint32_t Bst = Bbase + (uint32_t)(u % 3) * PV_BSS;
        #pragma unroll
        for (int s = 0; s < 4; s++) {
            uint32_t ah[2][4], bh[2][4], bl[2][4];
            #pragma unroll
            for (int mt = 0; mt < 2; mt++) {
                uint32_t o = aOff + (uint32_t)mt * 2048 + (uint32_t)s * 32;
                ldm_x4(ah[mt], Abase + sw128(o));
            }
            const uint32_t Bck = Bst + (uint32_t)(s >> 1) * 16384;
            #pragma unroll
            for (int np = 0; np < 2; np++) {
                uint32_t o = bOff + (uint32_t)np * 2048 + (uint32_t)(s & 1) * 32;
                ldm_x4(bh[np], Bck + sw128(o));
                ldm_x4(bl[np], Bck + sw128(o + 64));
            }
            #pragma unroll
            for (int mt = 0; mt < 2; mt++)
                #pragma unroll
                for (int nt = 0; nt < 4; nt++) {
                    const int np = nt >> 1, ix = (nt & 1) * 2;
                    MMA16816H(acc[mt][nt], ah[mt], bh[np][ix], bh[np][ix+1]);
                }
            #pragma unroll
            for (int mt = 0; mt < 2; mt++)
                #pragma unroll
                for (int nt = 0; nt < 4; nt++) {
                    const int np = nt >> 1, ix = (nt & 1) * 2;
                    MMA16816H(acc[mt][nt], ah[mt], bl[np][ix], bl[np][ix+1]);
                }
        }
    }

    #pragma unroll
    for (int mt = 0; mt < 2; mt++) {
        const int r0 = rowBase + warpM + mt * 16 + (lt >> 2);
        #pragma unroll
        for (int nt = 0; nt < 4; nt++) {
            const int cc = colBase + warpN + nt * 8 + (lt & 3) * 2;
            *(float2*)&C[(size_t)r0 * UDIM + cc] =
                make_float2(acc[mt][nt][0], acc[mt][nt][1]);
            *(float2*)&C[(size_t)(r0 + 8) * UDIM + cc] =
                make_float2(acc[mt][nt][2], acc[mt][nt][3]);
        }
    }
}

// ---------------- split fp32 -> packed-split bf16 ---------------------------
__global__ __launch_bounds__(256)
void split_pack(const float* __restrict__ in, unsigned char* __restrict__ out, int Kelems)
{
    const size_t idx = ((size_t)blockIdx.x * 256 + threadIdx.x) * 8;
    const size_t row = idx / Kelems;
    const int k0 = (int)(idx % Kelems);
    float4 f0 = *(const float4*)(in + idx);
    float4 f1 = *(const float4*)(in + idx + 4);
    uint2 h0, l0, h1, l1;
    split4(f0, h0, l0);
    split4(f1, h1, l1);
    unsigned char* p = out + row * ((size_t)Kelems * 4) + (k0 >> 5) * 128 + (k0 & 31) * 2;
    *(uint4*)p        = make_uint4(h0.x, h0.y, h1.x, h1.y);
    *(uint4*)(p + 64) = make_uint4(l0.x, l0.y, l1.x, l1.y);
}

// ---------------- transpose + split (bf16 or fp16 limbs) --------------------
template<int F16>
__global__ __launch_bounds__(256)
void transpose_split(const float* __restrict__ in, unsigned char* __restrict__ out,
                     int R, int C, size_t sIn, size_t sOut)
{
    __shared__ float t[32][33];
    in  += (size_t)blockIdx.z * sIn;
    out += (size_t)blockIdx.z * sOut;
    const int tid = threadIdx.x;
    const int tx = tid & 31, ty = tid >> 5;
    int x = blockIdx.x * 32 + tx;
    int y = blockIdx.y * 32 + ty;
    #pragma unroll
    for (int j = 0; j < 32; j += 8)
        t[ty + j][tx] = in[(size_t)(y + j) * C + x];
    __syncthreads();

    const int wr = tid >> 3;
    const int wg = tid & 7;
    float f0 = t[wg*4 + 0][wr];
    float f1 = t[wg*4 + 1][wr];
    float f2 = t[wg*4 + 2][wr];
    float f3 = t[wg*4 + 3][wr];
    uint32_t h0, l0, h1, l1;
    if (F16) { split2h(f0, f1, h0, l0); split2h(f2, f3, h1, l1); }
    else     { split2 (f0, f1, h0, l0); split2 (f2, f3, h1, l1); }
    const size_t pitch = (size_t)R * 4;
    unsigned char* p = out + (size_t)(blockIdx.x * 32 + wr) * pitch
                           + (size_t)blockIdx.y * 128 + wg * 8;
    *(uint2*)p        = make_uint2(h0, h1);
    *(uint2*)(p + 64) = make_uint2(l0, l1);
}

// ---------------- launch ----------------------------------------------------
extern "C" void kernel_launch(void* const* d_in, const int* in_sizes, int n_in,
                              void* d_out, int out_size)
{
    const float* x  = (const float*)d_in[0];
    const float* Wq = (const float*)d_in[1];
    const float* Wk = (const float*)d_in[2];
    const float* Wv = (const float*)d_in[3];
    float* out = (float*)d_out;

    unsigned char *xps, *wps, *qps, *kps, *vtps;
    float *v, *s, *shift;
    float2 *part;
    cudaGetSymbolAddress((void**)&xps,  g_xps);
    cudaGetSymbolAddress((void**)&wps,  g_wps);
    cudaGetSymbolAddress((void**)&qps,  g_qps);
    cudaGetSymbolAddress((void**)&kps,  g_kps);
    cudaGetSymbolAddress((void**)&v,    g_v);
    cudaGetSymbolAddress((void**)&vtps, g_vtps);
    cudaGetSymbolAddress((void**)&s,    g_s);
    cudaGetSymbolAddress((void**)&part, g_part);
    cudaGetSymbolAddress((void**)&shift, g_shift);

    cudaFuncSetAttribute(gemm_ps<2>, cudaFuncAttributeMaxDynamicSharedMemorySize, SMEM_GEMM);
    cudaFuncSetAttribute(gemm_ps<3>, cudaFuncAttributeMaxDynamicSharedMemorySize, SMEM_GEMM);
    cudaFuncSetAttribute(gemm_pv2,   cudaFuncAttributeMaxDynamicSharedMemorySize, SMEM_PV2);

    const size_t WPS = (size_t)UDIM * DIM * 4;

    // 1) split x; transpose+split weights (bf16 limbs)
    split_pack<<<(MROWS*DIM)/(256*8), 256>>>(x, xps, DIM);
    transpose_split<0><<<dim3(UDIM/32, DIM/32, 1), 256>>>(Wq, wps + 0*WPS, DIM, UDIM, 0, 0);
    transpose_split<0><<<dim3(UDIM/32, DIM/32, 1), 256>>>(Wk, wps + 1*WPS, DIM, UDIM, 0, 0);
    transpose_split<0><<<dim3(UDIM/32, DIM/32, 1), 256>>>(Wv, wps + 2*WPS, DIM, UDIM, 0, 0);

    // 2) fused QKV with router epilogue
    {
        dim3 g(768/128, MROWS/128, 1);
        gemm_ps<3><<<g, 512, SMEM_GEMM>>>(xps, wps, nullptr, qps, kps, v, nullptr,
                                          DIM, DIM*4, DIM*4, 0, 0, 0, 0);
    }

    // 3) v -> vt fp16 limbs per batch
    transpose_split<1><<<dim3(UDIM/32, SEQ/32, BATCH), 256>>>(v, vtps, SEQ, UDIM,
        (size_t)SEQ*UDIM, (size_t)UDIM*SEQ*4);

    // 4) scores = Q K^T with fused row stats
    {
        dim3 g(SEQ/128, SEQ/128, BATCH);
        gemm_ps<2><<<g, 512, SMEM_GEMM>>>(qps, kps, s, nullptr, nullptr, nullptr, part,
                                          UDIM, UDIM*4, UDIM*4, SEQ,
                                          (size_t)SEQ*UDIM*4, (size_t)SEQ*UDIM*4,
                                          (size_t)SEQ*SEQ);
    }

    // 5) combine stats -> shift
    rowstat_combine<<<MROWS/256, 256>>>(part, shift);

    // 6) out = softmax(S) V, fp16 2-term, fused poly-exp
    {
        dim3 g(UDIM/128, SEQ/128, BATCH);
        gemm_pv2<<<g, 512, SMEM_PV2>>>(s, shift, vtps, out,
                                       (size_t)SEQ*SEQ, (size_t)UDIM*SEQ*4,
                                       (size_t)SEQ*UDIM);
    }
}